// round 15
// baseline (speedup 1.0000x reference)
#include <cuda_runtime.h>
#include <math.h>
#include <stdint.h>

#define NA 16
#define OBSF 128
#define STATE 256
#define EMBED 32
#define NHID 32
#define BTOT 8192
#define ALPHA 0.2f
#define NEGV -9.0e15f
#define FULLM 0xffffffffu

// ---------------- scratch (device globals) ----------------
__device__ float g_z[(size_t)BTOT * NA * 128];       // 64 MB   att2@xcat1 (tf32 bits)
__device__ float g_ball[(size_t)BTOT * 512];         // 16 MB   b_all pre-bias
__device__ float g_wf[(size_t)BTOT * 512];           // 16 MB   |logsoftmax(gf out)|
__device__ float g_hidp[(size_t)BTOT * 2 * 512];     // 32 MB   partial hidden sums
__device__ float g_Bheads[128 * 256];                // packed head weights (tf32 bits)
__device__ float g_BhbT[256 * 512];                  // hb_W transposed (tf32 bits)
__device__ float g_Wout32[128 * 512];                // g1_Wout (tf32 bits)
__device__ float g_gfW32[128 * 32];                  // gf_Wout (tf32 bits)
__device__ float g_wa[256];                          // wa1 (128) | wa2 (128), fp32

__device__ __forceinline__ uint32_t f2tf32(float f) {
    uint32_t u; asm("cvt.rna.tf32.f32 %0, %1;" : "=r"(u) : "f"(f)); return u;
}
__device__ __forceinline__ float tf32f(float f) { return __uint_as_float(f2tf32(f)); }

__device__ __forceinline__ void mma_16n8k8(float* c,
    uint32_t a0, uint32_t a1, uint32_t a2, uint32_t a3,
    uint32_t b0, uint32_t b1)
{
    asm volatile(
        "mma.sync.aligned.m16n8k8.row.col.f32.tf32.tf32.f32 "
        "{%0,%1,%2,%3}, {%4,%5,%6,%7}, {%8,%9}, {%0,%1,%2,%3};"
        : "+f"(c[0]), "+f"(c[1]), "+f"(c[2]), "+f"(c[3])
        : "r"(a0), "r"(a1), "r"(a2), "r"(a3), "r"(b0), "r"(b1));
}

__device__ __forceinline__ float elu1(float v) {
    return v > 0.f ? v : (__expf(v) - 1.f);
}

__device__ __forceinline__ void cp16(uint32_t smem_addr, const void* gptr) {
    asm volatile("cp.async.ca.shared.global [%0], [%1], 16;\n"
                 :: "r"(smem_addr), "l"(gptr));
}
#define CP_COMMIT() asm volatile("cp.async.commit_group;\n" ::: "memory")
template <int N> __device__ __forceinline__ void cp_wait() {
    asm volatile("cp.async.wait_group %0;\n" :: "n"(N) : "memory");
}

// =====================================================================
// K0: pack weights (tf32-converted) + wa vectors
// =====================================================================
__global__ void pack_kernel(const float* __restrict__ g1_Wh, const float* __restrict__ gf_Wh,
                            const float* __restrict__ g1_Wout, const float* __restrict__ g1_aout,
                            const float* __restrict__ gf_Wout, const float* __restrict__ hb_W)
{
    int t = threadIdx.x, bid = blockIdx.x;
    int gid = bid * 256 + t;
    for (int idx = gid; idx < 128 * 256; idx += 64 * 256) {
        int k = idx >> 8, c = idx & 255;
        float v = (c < 128) ? g1_Wh[(c >> 5) * 4096 + k * 32 + (c & 31)]
                            : gf_Wh[((c - 128) >> 5) * 4096 + k * 32 + (c & 31)];
        g_Bheads[idx] = tf32f(v);
    }
    for (int idx = gid; idx < 256 * 512; idx += 64 * 256) {
        int k = idx >> 9, n = idx & 511;
        g_BhbT[idx] = tf32f(hb_W[n * 256 + k]);
    }
    for (int idx = gid; idx < 128 * 512; idx += 64 * 256)
        g_Wout32[idx] = tf32f(g1_Wout[idx]);
    for (int idx = gid; idx < 128 * 32; idx += 64 * 256)
        g_gfW32[idx] = tf32f(gf_Wout[idx]);
    if (bid == 0) {
        int wp = t >> 5, ln = t & 31;
        for (int d = wp; d < 256; d += 8) {
            int k = d & 127, half = d >> 7;
            const float* ap = g1_aout + half * 512;
            const float* wr = g1_Wout + (size_t)k * 512;
            float acc = 0.f;
            for (int c = ln; c < 512; c += 32) acc = fmaf(wr[c], ap[c], acc);
            #pragma unroll
            for (int o = 16; o; o >>= 1) acc += __shfl_down_sync(FULLM, acc, o);
            if (ln == 0) g_wa[half * 128 + k] = acc;
        }
    }
}

// =====================================================================
// TF32 GEMM (used for b_all only): C = A @ B, B PRE-CONVERTED.
// =====================================================================
#define LDA 36
#define LDB 136

__global__ __launch_bounds__(256) void gemm_tf32(
    const float* __restrict__ A, const float* __restrict__ B, float* __restrict__ C,
    int M, int K, int N)
{
    __shared__ uint32_t As[128 * LDA];
    __shared__ uint32_t Bs[32 * LDB];
    int t = threadIdx.x;
    int lane = t & 31, w = t >> 5;
    int wm = w & 3, wn = w >> 2;
    int bm = blockIdx.y * 128, bn = blockIdx.x * 128;
    int r = lane >> 2, cq = lane & 3;

    float acc[2][8][4];
    #pragma unroll
    for (int mi = 0; mi < 2; mi++)
        #pragma unroll
        for (int ni = 0; ni < 8; ni++)
            #pragma unroll
            for (int j = 0; j < 4; j++) acc[mi][ni][j] = 0.f;

    for (int k0 = 0; k0 < K; k0 += 32) {
        #pragma unroll
        for (int l = 0; l < 4; l++) {
            int idx = t + l * 256;
            int row = idx >> 3, q = idx & 7;
            float4 v = *reinterpret_cast<const float4*>(A + (size_t)(bm + row) * K + k0 + q * 4);
            uint32_t* p = &As[row * LDA + q * 4];
            p[0] = f2tf32(v.x); p[1] = f2tf32(v.y); p[2] = f2tf32(v.z); p[3] = f2tf32(v.w);
        }
        #pragma unroll
        for (int l = 0; l < 4; l++) {
            int idx = t + l * 256;
            int row = idx >> 5, q = idx & 31;
            uint4 v = *reinterpret_cast<const uint4*>(B + (size_t)(k0 + row) * N + bn + q * 4);
            uint32_t* p = &Bs[row * LDB + q * 4];
            p[0] = v.x; p[1] = v.y; p[2] = v.z; p[3] = v.w;
        }
        __syncthreads();
        #pragma unroll
        for (int kk = 0; kk < 32; kk += 8) {
            uint32_t a[2][4];
            #pragma unroll
            for (int mi = 0; mi < 2; mi++) {
                int rb = wm * 32 + mi * 16;
                a[mi][0] = As[(rb + r) * LDA + kk + cq];
                a[mi][1] = As[(rb + r + 8) * LDA + kk + cq];
                a[mi][2] = As[(rb + r) * LDA + kk + cq + 4];
                a[mi][3] = As[(rb + r + 8) * LDA + kk + cq + 4];
            }
            #pragma unroll
            for (int ni = 0; ni < 8; ni++) {
                int cb = wn * 64 + ni * 8;
                uint32_t b0 = Bs[(kk + cq) * LDB + cb + r];
                uint32_t b1 = Bs[(kk + 4 + cq) * LDB + cb + r];
                #pragma unroll
                for (int mi = 0; mi < 2; mi++)
                    mma_16n8k8(acc[mi][ni], a[mi][0], a[mi][1], a[mi][2], a[mi][3], b0, b1);
            }
        }
        __syncthreads();
    }
    #pragma unroll
    for (int mi = 0; mi < 2; mi++) {
        int rb = bm + wm * 32 + mi * 16 + r;
        #pragma unroll
        for (int ni = 0; ni < 8; ni++) {
            int cb = bn + wn * 64 + ni * 8 + 2 * cq;
            *reinterpret_cast<float2*>(C + (size_t)rb * N + cb) =
                make_float2(acc[mi][ni][0], acc[mi][ni][1]);
            *reinterpret_cast<float2*>(C + (size_t)(rb + 8) * N + cb) =
                make_float2(acc[mi][ni][2], acc[mi][ni][3]);
        }
    }
}

// =====================================================================
// K1: FUSED head-projection + attention, BATCH PAIR per CTA.
// 512 threads, 16 warps: warp w -> (sub-batch sb = w>>3, head h = w&7).
// Dynamic smem 62,080 B; 2 CTAs/SM.
// =====================================================================
#define XCP 132
// float offsets within dynamic smem
#define A_BUF1 0                      // [2][16][132]
#define A_XCF  (A_BUF1 + 2*16*XCP)    // [2][16][132]
#define A_ATTW (A_XCF  + 2*16*XCP)    // [2][8][16][17]
#define A_ADJ  (A_ATTW + 2*8*16*17)   // [2][16][16]
#define A_AT2  (A_ADJ  + 2*256)       // [2][16][17]
#define A_WHF  (A_AT2  + 2*16*17)     // [2][16][34]
#define A_F1S  (A_WHF  + 2*16*34)     // [2][16]
#define A_F2S  (A_F1S  + 32)          // [2][16]
#define A_SA   (A_F2S  + 32)          // [8][64]
#define A_TOTAL (A_SA + 512)          // 15520 floats = 62,080 B

extern __shared__ float asmem[];

__global__ __launch_bounds__(512, 2) void attn_kernel(
    const float* __restrict__ obs_g, const float* __restrict__ adj_g,
    const float* __restrict__ g1_ah, const float* __restrict__ gf_ah,
    const float* __restrict__ gf_aout)
{
    int bb = blockIdx.x;                 // batch pair
    int b0 = bb * 2;
    int t = threadIdx.x;
    int lane = t & 31, w = t >> 5;
    int sb = w >> 3, h = w & 7;
    int r = lane >> 2, cq = lane & 3;

    float* buf1 = asmem + A_BUF1;
    float* xcfp = asmem + A_XCF;
    float* attw = asmem + A_ATTW;
    float* adjp = asmem + A_ADJ;
    float* at2  = asmem + A_AT2;
    float* whfp = asmem + A_WHF;
    float* f1sp = asmem + A_F1S;
    float* f2sp = asmem + A_F2S;
    float* sap  = asmem + A_SA;

    #define BUF1(s,i,k) buf1[(s)*16*XCP + (i)*XCP + (k)]
    #define XCFS(s,i,k) xcfp[(s)*16*XCP + (i)*XCP + (k)]
    #define ATTW(s,hh,i,j) attw[(s)*2176 + (hh)*272 + (i)*17 + (j)]
    #define ADJS(s,i,j) adjp[(s)*256 + (i)*16 + (j)]
    #define AT2S(s,i,j) at2[(s)*272 + (i)*17 + (j)]
    #define WHFS(s,i,c) whfp[(s)*544 + (i)*34 + (c)]

    // ---- loads: obs for both batches (contiguous), adj, head a-vectors ----
    {
        const float4* src = reinterpret_cast<const float4*>(obs_g + (size_t)bb * 4096);
        #pragma unroll
        for (int l = 0; l < 2; l++) {
            int idx4 = t + l * 512;              // 0..1023
            int s = idx4 >> 9, within = idx4 & 511;
            int row = within >> 5, c4 = (within & 31) * 4;
            float4 v = src[idx4];
            BUF1(s, row, c4)     = tf32f(v.x);
            BUF1(s, row, c4 + 1) = tf32f(v.y);
            BUF1(s, row, c4 + 2) = tf32f(v.z);
            BUF1(s, row, c4 + 3) = tf32f(v.w);
        }
    }
    {
        int s = t >> 8, e = t & 255;
        ADJS(s, e >> 4, e & 15) = adj_g[(size_t)bb * 512 + t];
        int hh = t >> 6, c = t & 63;
        if (t < 512) sap[t] = (hh < 4) ? g1_ah[hh * 64 + c] : gf_ah[(hh - 4) * 64 + c];
    }
    __syncthreads();

    // ---- phase 1: wh fragment = obs @ Bheads_h (16x32, K=128) ----
    float acc1[4][4];
    #pragma unroll
    for (int nt = 0; nt < 4; nt++)
        #pragma unroll
        for (int q = 0; q < 4; q++) acc1[nt][q] = 0.f;
    #pragma unroll
    for (int ks = 0; ks < 16; ks++) {
        int kk = ks * 8;
        uint32_t a0 = __float_as_uint(BUF1(sb, r, kk + cq));
        uint32_t a1 = __float_as_uint(BUF1(sb, r + 8, kk + cq));
        uint32_t a2 = __float_as_uint(BUF1(sb, r, kk + cq + 4));
        uint32_t a3 = __float_as_uint(BUF1(sb, r + 8, kk + cq + 4));
        #pragma unroll
        for (int nt = 0; nt < 4; nt++) {
            int cb = h * 32 + nt * 8;
            uint32_t b0 = __float_as_uint(__ldg(&g_Bheads[(kk + cq) * 256 + cb + r]));
            uint32_t b1 = __float_as_uint(__ldg(&g_Bheads[(kk + 4 + cq) * 256 + cb + r]));
            mma_16n8k8(acc1[nt], a0, a1, a2, a3, b0, b1);
        }
    }

    // ---- scores from fragments: quad-reduce + spread ----
    float facc;
    {
        const float* av = &sap[h * 64];
        float pf1r = 0.f, pf1r8 = 0.f, pf2r = 0.f, pf2r8 = 0.f;
        #pragma unroll
        for (int nt = 0; nt < 4; nt++) {
            float2 a1v = *reinterpret_cast<const float2*>(av + nt * 8 + 2 * cq);
            float2 a2v = *reinterpret_cast<const float2*>(av + 32 + nt * 8 + 2 * cq);
            pf1r  = fmaf(acc1[nt][0], a1v.x, fmaf(acc1[nt][1], a1v.y, pf1r));
            pf1r8 = fmaf(acc1[nt][2], a1v.x, fmaf(acc1[nt][3], a1v.y, pf1r8));
            pf2r  = fmaf(acc1[nt][0], a2v.x, fmaf(acc1[nt][1], a2v.y, pf2r));
            pf2r8 = fmaf(acc1[nt][2], a2v.x, fmaf(acc1[nt][3], a2v.y, pf2r8));
        }
        #pragma unroll
        for (int mk = 1; mk <= 2; mk <<= 1) {
            pf1r  += __shfl_xor_sync(FULLM, pf1r,  mk);
            pf1r8 += __shfl_xor_sync(FULLM, pf1r8, mk);
            pf2r  += __shfl_xor_sync(FULLM, pf2r,  mk);
            pf2r8 += __shfl_xor_sync(FULLM, pf2r8, mk);
        }
        int j = lane & 15, half = lane >> 4;
        int src = (j & 7) * 4;
        float s1 = __shfl_sync(FULLM, pf1r,  src);
        float s2 = __shfl_sync(FULLM, pf1r8, src);
        float s3 = __shfl_sync(FULLM, pf2r,  src);
        float s4 = __shfl_sync(FULLM, pf2r8, src);
        facc = half ? ((j < 8) ? s3 : s4) : ((j < 8) ? s1 : s2);
    }
    __syncthreads();   // obs reads done; buf1 becomes xc1 below

    // ---- softmax (lanes j hold column att[.][j]) ----
    {
        int j = lane & 15;
        float f2j = __shfl_sync(FULLM, facc, 16 + j);
        float attc[NA];
        float m = -INFINITY;
        #pragma unroll
        for (int i = 0; i < NA; i++) {
            float f1i = __shfl_sync(FULLM, facc, i);
            float e = f1i + f2j;
            e = e > 0.f ? e : ALPHA * e;
            e = (ADJS(sb, i, j) > 0.f) ? e : NEGV;
            attc[i] = e; m = fmaxf(m, e);
        }
        float s = 0.f;
        #pragma unroll
        for (int i = 0; i < NA; i++) { float x = __expf(attc[i] - m); attc[i] = x; s += x; }
        float inv = 1.f / s;
        if (lane < 16) {
            #pragma unroll
            for (int i = 0; i < NA; i++) ATTW(sb, h, i, j) = tf32f(attc[i] * inv);
        }
        __syncwarp();
    }

    // ---- head-out: out = att @ wh ; B-frags shuffled from acc1 ----
    {
        float acc2[4][4];
        #pragma unroll
        for (int nt = 0; nt < 4; nt++)
            #pragma unroll
            for (int q = 0; q < 4; q++) acc2[nt][q] = 0.f;
        int src0 = cq * 4 + (r >> 1);
        int src1 = (cq + 4) * 4 + (r >> 1);
        bool odd = (r & 1);
        #pragma unroll
        for (int ks2 = 0; ks2 < 2; ks2++) {
            int kk2 = ks2 * 8;
            uint32_t a0 = __float_as_uint(ATTW(sb, h, r, kk2 + cq));
            uint32_t a1 = __float_as_uint(ATTW(sb, h, r + 8, kk2 + cq));
            uint32_t a2 = __float_as_uint(ATTW(sb, h, r, kk2 + cq + 4));
            uint32_t a3 = __float_as_uint(ATTW(sb, h, r + 8, kk2 + cq + 4));
            #pragma unroll
            for (int nt = 0; nt < 4; nt++) {
                float lo = acc1[nt][ks2 * 2];
                float hi = acc1[nt][ks2 * 2 + 1];
                float v0l = __shfl_sync(FULLM, lo, src0);
                float v0h = __shfl_sync(FULLM, hi, src0);
                float v1l = __shfl_sync(FULLM, lo, src1);
                float v1h = __shfl_sync(FULLM, hi, src1);
                uint32_t b0 = f2tf32(odd ? v0h : v0l);
                uint32_t b1 = f2tf32(odd ? v1h : v1l);
                mma_16n8k8(acc2[nt], a0, a1, a2, a3, b0, b1);
            }
        }
        float* base = (h < 4) ? &BUF1(sb, 0, h * 32) : &XCFS(sb, 0, (h - 4) * 32);
        #pragma unroll
        for (int nt = 0; nt < 4; nt++) {
            int col = nt * 8 + 2 * cq;
            *reinterpret_cast<float2*>(base + r * XCP + col) =
                make_float2(tf32f(elu1(acc2[nt][0])), tf32f(elu1(acc2[nt][1])));
            *reinterpret_cast<float2*>(base + (r + 8) * XCP + col) =
                make_float2(tf32f(elu1(acc2[nt][2])), tf32f(elu1(acc2[nt][3])));
        }
    }
    __syncthreads();

    // ---- g1-out scores: 64 dots (2 batches x 32) across 16 warps ----
    #pragma unroll
    for (int rr = 0; rr < 4; rr++) {
        int d2 = w * 4 + rr;                // 0..63
        int s2 = d2 >> 5, dd = d2 & 31;
        int i = dd & 15, half = dd >> 4;
        const float* wav = g_wa + half * 128;
        float acc = 0.f;
        #pragma unroll
        for (int k = lane; k < 128; k += 32) acc = fmaf(BUF1(s2, i, k), wav[k], acc);
        #pragma unroll
        for (int o = 16; o; o >>= 1) acc += __shfl_down_sync(FULLM, acc, o);
        if (lane == 0) { if (half) f2sp[s2 * 16 + i] = acc; else f1sp[s2 * 16 + i] = acc; }
    }
    __syncthreads();
    if (t < 32) {
        int s2 = t >> 4, j = t & 15;
        float ev[NA]; float m = -INFINITY;
        #pragma unroll
        for (int i = 0; i < NA; i++) {
            float e = f1sp[s2 * 16 + i] + f2sp[s2 * 16 + j];
            e = e > 0.f ? e : ALPHA * e;
            e = (ADJS(s2, i, j) > 0.f) ? e : NEGV;
            ev[i] = e; m = fmaxf(m, e);
        }
        float s = 0.f;
        #pragma unroll
        for (int i = 0; i < NA; i++) { float x = __expf(ev[i] - m); ev[i] = x; s += x; }
        float inv = 1.f / s;
        #pragma unroll
        for (int i = 0; i < NA; i++) AT2S(s2, i, j) = tf32f(ev[i] * inv);
    }
    __syncthreads();

    // ---- z = att2 @ xc1: warp w -> (sb, cols [16*(w&7), +16)) ----
    {
        int wc = w & 7;
        float acc[2][4];
        #pragma unroll
        for (int nt = 0; nt < 2; nt++)
            #pragma unroll
            for (int q = 0; q < 4; q++) acc[nt][q] = 0.f;
        #pragma unroll
        for (int ks = 0; ks < 2; ks++) {
            int kk = ks * 8;
            uint32_t a0 = __float_as_uint(AT2S(sb, r, kk + cq));
            uint32_t a1 = __float_as_uint(AT2S(sb, r + 8, kk + cq));
            uint32_t a2 = __float_as_uint(AT2S(sb, r, kk + cq + 4));
            uint32_t a3 = __float_as_uint(AT2S(sb, r + 8, kk + cq + 4));
            #pragma unroll
            for (int nt = 0; nt < 2; nt++) {
                int cb = wc * 16 + nt * 8;
                uint32_t b0 = __float_as_uint(BUF1(sb, kk + cq, cb + r));
                uint32_t b1 = __float_as_uint(BUF1(sb, kk + 4 + cq, cb + r));
                mma_16n8k8(acc[nt], a0, a1, a2, a3, b0, b1);
            }
        }
        float* zdst = g_z + (size_t)(b0 + sb) * 2048;
        #pragma unroll
        for (int nt = 0; nt < 2; nt++) {
            int col = wc * 16 + nt * 8 + 2 * cq;
            *reinterpret_cast<float2*>(zdst + r * 128 + col) =
                make_float2(tf32f(acc[nt][0]), tf32f(acc[nt][1]));
            *reinterpret_cast<float2*>(zdst + (r + 8) * 128 + col) =
                make_float2(tf32f(acc[nt][2]), tf32f(acc[nt][3]));
        }
    }

    // ---- whf = xcf @ gf_Wout: warps (w&7)<4 for each sb ----
    if ((w & 7) < 4) {
        int cb = (w & 3) * 8;
        float acc[4] = {0.f, 0.f, 0.f, 0.f};
        #pragma unroll
        for (int ks = 0; ks < 16; ks++) {
            int kk = ks * 8;
            uint32_t a0 = __float_as_uint(XCFS(sb, r, kk + cq));
            uint32_t a1 = __float_as_uint(XCFS(sb, r + 8, kk + cq));
            uint32_t a2 = __float_as_uint(XCFS(sb, r, kk + cq + 4));
            uint32_t a3 = __float_as_uint(XCFS(sb, r + 8, kk + cq + 4));
            uint32_t b0 = __float_as_uint(g_gfW32[(kk + cq) * 32 + cb + r]);
            uint32_t b1 = __float_as_uint(g_gfW32[(kk + 4 + cq) * 32 + cb + r]);
            mma_16n8k8(acc, a0, a1, a2, a3, b0, b1);
        }
        int col = cb + 2 * cq;
        *reinterpret_cast<float2*>(&WHFS(sb, r, col)) = make_float2(acc[0], acc[1]);
        *reinterpret_cast<float2*>(&WHFS(sb, r + 8, col)) = make_float2(acc[2], acc[3]);
    }
    __syncthreads();

    // ---- gf attention finish: warp 0 -> sb0, warp 8 -> sb1 ----
    if ((w & 7) == 0) {
        int d = lane & 15, half = lane >> 4;
        const float* av = gf_aout + half * 32;
        float fac = 0.f;
        #pragma unroll
        for (int c = 0; c < 32; c++) fac = fmaf(WHFS(sb, d, c), av[c], fac);
        int j = lane & 15;
        float f2j = __shfl_sync(FULLM, fac, 16 + j);
        float attc[NA];
        float m = -INFINITY;
        #pragma unroll
        for (int i = 0; i < NA; i++) {
            float f1i = __shfl_sync(FULLM, fac, i);
            float e = f1i + f2j;
            e = e > 0.f ? e : ALPHA * e;
            e = (ADJS(sb, i, j) > 0.f) ? e : NEGV;
            attc[i] = e; m = fmaxf(m, e);
        }
        float s = 0.f;
        #pragma unroll
        for (int i = 0; i < NA; i++) { float x = __expf(attc[i] - m); attc[i] = x; s += x; }
        float inv = 1.f / s;
        #pragma unroll
        for (int i = 0; i < NA; i++) attc[i] *= inv;
        int c = lane;
        float o2[NA];
        float mm = -INFINITY;
        #pragma unroll
        for (int i = 0; i < NA; i++) {
            float acc = 0.f;
            #pragma unroll
            for (int n = 0; n < NA; n++) {
                float a_in = __shfl_sync(FULLM, attc[i], n);
                acc = fmaf(a_in, WHFS(sb, n, c), acc);
            }
            acc = elu1(acc);
            o2[i] = acc; mm = fmaxf(mm, acc);
        }
        float ss = 0.f;
        #pragma unroll
        for (int i = 0; i < NA; i++) ss += __expf(o2[i] - mm);
        float lse = mm + __logf(ss);
        #pragma unroll
        for (int i = 0; i < NA; i++)
            g_wf[(size_t)(b0 + sb) * 512 + i * 32 + c] = fabsf(o2[i] - lse);
    }
}

// =====================================================================
// K2: GEMM3 half-N CTAs (unchanged from R13).
// =====================================================================
#define LDB3H 264
#define ASTG  (64 * LDA)
#define BSTGH (32 * LDB3H)

extern __shared__ char g3smem[];

__global__ __launch_bounds__(256, 2) void gemm3_half_kernel(
    const float* __restrict__ A,
    const float* __restrict__ Wout,
    const float* __restrict__ agent_qs)
{
    uint32_t* Sm = reinterpret_cast<uint32_t*>(g3smem);
    float*    Ds = reinterpret_cast<float*>(g3smem);
    uint32_t smem_u32 = (uint32_t)__cvta_generic_to_shared(g3smem);

    __shared__ float qs_s[4][NA];

    int t = threadIdx.x;
    int lane = t & 31, w = t >> 5;
    int wm = w & 1, wn = w >> 1;
    int r = lane >> 2, cq = lane & 3;
    int half = blockIdx.x;
    int bm = blockIdx.y * 64;
    int b0 = blockIdx.y * 4;
    int bn = half * 256;

    if (t < 64) qs_s[t >> 4][t & 15] = agent_qs[(size_t)(b0 + (t >> 4)) * NA + (t & 15)];

    int arow = t >> 3, aq = t & 7;
    const float* agsrc = A + (size_t)(bm + arow) * 128 + aq * 4;
    const float* agsrc2 = A + (size_t)(bm + arow + 32) * 128 + aq * 4;
    uint32_t adst1 = (uint32_t)(arow * LDA + aq * 4) * 4;
    uint32_t adst2 = (uint32_t)((arow + 32) * LDA + aq * 4) * 4;

    #define LOAD_STAGE_H(s, k0)                                                 \
        do {                                                                    \
            uint32_t abase = smem_u32 + (uint32_t)((s) * ASTG) * 4;             \
            cp16(abase + adst1, agsrc + (k0));                                  \
            cp16(abase + adst2, agsrc2 + (k0));                                 \
            uint32_t bbase = smem_u32 + (uint32_t)(2 * ASTG + (s) * BSTGH) * 4; \
            _Pragma("unroll")                                                   \
            for (int l = 0; l < 8; l++) {                                       \
                int idx = t + l * 256;                                          \
                int brow = idx >> 6, bq = idx & 63;                             \
                cp16(bbase + (uint32_t)(brow * LDB3H + bq * 4) * 4,             \
                     Wout + (size_t)((k0) + brow) * 512 + bn + bq * 4);         \
            }                                                                   \
            CP_COMMIT();                                                        \
        } while (0)

    float acc[2][8][4];
    #pragma unroll
    for (int mi = 0; mi < 2; mi++)
        #pragma unroll
        for (int ni = 0; ni < 8; ni++)
            #pragma unroll
            for (int j = 0; j < 4; j++) acc[mi][ni][j] = 0.f;

    LOAD_STAGE_H(0, 0);
    LOAD_STAGE_H(1, 32);

    #pragma unroll
    for (int it = 0; it < 4; it++) {
        int s = it & 1;
        if (it < 3) cp_wait<1>(); else cp_wait<0>();
        __syncthreads();
        const uint32_t* As = Sm + s * ASTG;
        const uint32_t* Bs = Sm + 2 * ASTG + s * BSTGH;
        #pragma unroll
        for (int kk = 0; kk < 32; kk += 8) {
            uint32_t a[2][4];
            #pragma unroll
            for (int mi = 0; mi < 2; mi++) {
                int rb = wm * 32 + mi * 16;
                a[mi][0] = As[(rb + r) * LDA + kk + cq];
                a[mi][1] = As[(rb + r + 8) * LDA + kk + cq];
                a[mi][2] = As[(rb + r) * LDA + kk + cq + 4];
                a[mi][3] = As[(rb + r + 8) * LDA + kk + cq + 4];
            }
            #pragma unroll
            for (int ni = 0; ni < 8; ni++) {
                int cb = wn * 64 + ni * 8;
                uint32_t b0r = Bs[(kk + cq) * LDB3H + cb + r];
                uint32_t b1r = Bs[(kk + 4 + cq) * LDB3H + cb + r];
                #pragma unroll
                for (int mi = 0; mi < 2; mi++)
                    mma_16n8k8(acc[mi][ni], a[mi][0], a[mi][1], a[mi][2], a[mi][3], b0r, b1r);
            }
        }
        __syncthreads();
        if (it + 2 < 4) LOAD_STAGE_H(s, (it + 2) * 32);
    }

    #pragma unroll
    for (int mi = 0; mi < 2; mi++) {
        int row0 = wm * 32 + mi * 16 + r;
        #pragma unroll
        for (int ni = 0; ni < 8; ni++) {
            int col = wn * 64 + ni * 8 + 2 * cq;
            *reinterpret_cast<float2*>(&Ds[row0 * 256 + col]) =
                make_float2(elu1(acc[mi][ni][0]), elu1(acc[mi][ni][1]));
            *reinterpret_cast<float2*>(&Ds[(row0 + 8) * 256 + col]) =
                make_float2(elu1(acc[mi][ni][2]), elu1(acc[mi][ni][3]));
        }
    }
    __syncthreads();

    #pragma unroll
    for (int p = 0; p < 4; p++) {
        int tt = t + p * 256;
        int bl = tt >> 8, c = tt & 255;
        float* col = Ds + (bl * 16) * 256 + c;
        float v[NA]; float m = -INFINITY;
        #pragma unroll
        for (int i = 0; i < NA; i++) { v[i] = col[i * 256]; m = fmaxf(m, v[i]); }
        float s = 0.f;
        #pragma unroll
        for (int i = 0; i < NA; i++) s += __expf(v[i] - m);
        float lse = m + __logf(s);
        #pragma unroll
        for (int i = 0; i < NA; i++) col[i * 256] = fabsf(v[i] - lse);
    }
    __syncthreads();

    {
        int e = lane;
        #pragma unroll
        for (int ai = 0; ai < 2; ai++) {
            int i = w + ai * 8;
            #pragma unroll
            for (int bl = 0; bl < 4; bl++) {
                const float* row = Ds + (bl * 16 + i) * 256;
                float p = 0.f;
                #pragma unroll
                for (int np = 0; np < 8; np++)
                    p = fmaf(qs_s[bl][8 * half + np], row[np * 32 + e], p);
                g_hidp[(((size_t)(b0 + bl) * 2 + half) * 16 + i) * 32 + e] = p;
            }
        }
    }
}

// =====================================================================
// K3: final mix (unchanged from R13).
// =====================================================================
__global__ __launch_bounds__(256) void mix_final_kernel(
    const float* __restrict__ states,
    const float* __restrict__ wn_w, const float* __restrict__ wn_b,
    const float* __restrict__ hb_b,
    const float* __restrict__ v1_w, const float* __restrict__ v1_b,
    const float* __restrict__ v2_w, const float* __restrict__ v2_b,
    float* __restrict__ out)
{
    int b = blockIdx.x;
    int t = threadIdx.x;
    int lane = t & 31, w = t >> 5;

    __shared__ float st[STATE];
    __shared__ float yv[NA], disv[NA], vpart[32];

    st[t] = (t < 256) ? states[(size_t)b * 256 + t] : 0.f;
    __syncthreads();

    {
        int e = lane;
        #pragma unroll
        for (int ai = 0; ai < 2; ai++) {
            int i = w + ai * 8;
            size_t base0 = (((size_t)b * 2 + 0) * 16 + i) * 32 + e;
            size_t base1 = (((size_t)b * 2 + 1) * 16 + i) * 32 + e;
            float hp = g_hidp[base0] + g_hidp[base1]
                     + g_ball[(size_t)b * 512 + i * 32 + e] + hb_b[i * 32 + e];
            hp = elu1(hp);
            float prod = hp * g_wf[(size_t)b * 512 + i * 32 + e];
            #pragma unroll
            for (int o = 16; o; o >>= 1) prod += __shfl_down_sync(FULLM, prod, o);
            if (lane == 0) yv[i] = prod;
        }
    }

    {
        #pragma unroll
        for (int rr = 0; rr < 2; rr++) {
            int n = w * 2 + rr;
            float acc2 = 0.f;
            #pragma unroll
            for (int s_ = lane; s_ < 256; s_ += 32)
                acc2 = fmaf(st[s_], wn_w[n * 256 + s_], acc2);
            #pragma unroll
            for (int o = 16; o; o >>= 1) acc2 += __shfl_down_sync(FULLM, acc2, o);
            if (lane == 0) disv[n] = fabsf(acc2 + wn_b[n]);
        }
        #pragma unroll
        for (int rr = 0; rr < 4; rr++) {
            int n = w * 4 + rr;
            float acc2 = 0.f;
            #pragma unroll
            for (int s_ = lane; s_ < 256; s_ += 32)
                acc2 = fmaf(st[s_], v1_w[n * 256 + s_], acc2);
            #pragma unroll
            for (int o = 16; o; o >>= 1) acc2 += __shfl_down_sync(FULLM, acc2, o);
            if (lane == 0) vpart[n] = fmaxf(acc2 + v1_b[n], 0.f);
        }
    }
    __syncthreads();

    if (t == 0) {
        float v = v2_b[0];
        #pragma unroll
        for (int h2 = 0; h2 < 32; h2++) v = fmaf(vpart[h2], v2_w[h2], v);
        float q = v;
        #pragma unroll
        for (int n = 0; n < NA; n++) q = fmaf(yv[n], disv[n], q);
        out[b] = q;
    }
}

// =====================================================================
extern "C" void kernel_launch(void* const* d_in, const int* in_sizes, int n_in,
                              void* d_out, int out_size)
{
    const float* agent_qs = (const float*)d_in[0];
    const float* states   = (const float*)d_in[1];
    const float* obs_ls   = (const float*)d_in[2];
    const float* adj_ls   = (const float*)d_in[3];
    const float* wn_w     = (const float*)d_in[4];
    const float* wn_b     = (const float*)d_in[5];
    const float* g1_Wh    = (const float*)d_in[6];
    const float* g1_ah    = (const float*)d_in[7];
    const float* g1_Wout  = (const float*)d_in[8];
    const float* g1_aout  = (const float*)d_in[9];
    const float* gf_Wh    = (const float*)d_in[10];
    const float* gf_ah    = (const float*)d_in[11];
    const float* gf_Wout  = (const float*)d_in[12];
    const float* gf_aout  = (const float*)d_in[13];
    const float* hb_W     = (const float*)d_in[14];
    const float* hb_b     = (const float*)d_in[15];
    const float* v1_w     = (const float*)d_in[16];
    const float* v1_b     = (const float*)d_in[17];
    const float* v2_w     = (const float*)d_in[18];
    const float* v2_b     = (const float*)d_in[19];
    float* out = (float*)d_out;

    float *p_z, *p_ball, *p_BhbT, *p_Wout32;
    cudaGetSymbolAddress((void**)&p_z,      g_z);
    cudaGetSymbolAddress((void**)&p_ball,   g_ball);
    cudaGetSymbolAddress((void**)&p_BhbT,   g_BhbT);
    cudaGetSymbolAddress((void**)&p_Wout32, g_Wout32);

    const int G3H_SMEM = (2 * ASTG + 2 * BSTGH) * 4;   // 86,016 B
    cudaFuncSetAttribute(gemm3_half_kernel,
                         cudaFuncAttributeMaxDynamicSharedMemorySize, G3H_SMEM);
    const int ATTN_SMEM = A_TOTAL * 4;                 // 62,080 B
    cudaFuncSetAttribute(attn_kernel,
                         cudaFuncAttributeMaxDynamicSharedMemorySize, ATTN_SMEM);

    pack_kernel<<<64, 256>>>(g1_Wh, gf_Wh, g1_Wout, g1_aout, gf_Wout, hb_W);

    // b_all = states(8192x256) @ hb_W^T(256x512)
    gemm_tf32<<<dim3(4, 64), 256>>>(states, p_BhbT, p_ball, BTOT, 256, 512);

    // fused head-projection + attention, batch pair per CTA
    attn_kernel<<<BTOT / 2, 512, ATTN_SMEM>>>(obs_ls, adj_ls, g1_ah, gf_ah, gf_aout);

    // D = Z @ Wout in half-N CTAs -> elu/logsoftmax/abs -> partial hidden
    gemm3_half_kernel<<<dim3(2, 2048), 256, G3H_SMEM>>>(p_z, p_Wout32, agent_qs);

    // combine partials + ball -> elu -> y; dis, V, q
    mix_final_kernel<<<BTOT, 256>>>(states, wn_w, wn_b, hb_b,
                                    v1_w, v1_b, v2_w, v2_b, out);
}

// round 17
// speedup vs baseline: 1.0750x; 1.0750x over previous
#include <cuda_runtime.h>
#include <math.h>
#include <stdint.h>

#define NA 16
#define OBSF 128
#define STATE 256
#define EMBED 32
#define NHID 32
#define BTOT 8192
#define ALPHA 0.2f
#define NEGV -9.0e15f
#define FULLM 0xffffffffu

// ---------------- scratch (device globals) ----------------
__device__ float g_z[(size_t)BTOT * NA * 128];       // 64 MB   att2@xcat1 (tf32 bits)
__device__ float g_ball[(size_t)BTOT * 512];         // 16 MB   b_all pre-bias
__device__ float g_wf[(size_t)BTOT * 512];           // 16 MB   |logsoftmax(gf out)|
__device__ float g_hidp[(size_t)BTOT * 2 * 512];     // 32 MB   partial hidden sums
__device__ float g_Bheads[128 * 256];                // packed head weights (tf32 bits)
__device__ float g_BhbT[256 * 512];                  // hb_W transposed (tf32 bits)
__device__ float g_Wout32[128 * 512];                // g1_Wout (tf32 bits)
__device__ float g_gfW32[128 * 32];                  // gf_Wout (tf32 bits)
__device__ float g_wa[256];                          // wa1 (128) | wa2 (128), fp32

__device__ __forceinline__ uint32_t f2tf32(float f) {
    uint32_t u; asm("cvt.rna.tf32.f32 %0, %1;" : "=r"(u) : "f"(f)); return u;
}
__device__ __forceinline__ float tf32f(float f) { return __uint_as_float(f2tf32(f)); }

__device__ __forceinline__ void mma_16n8k8(float* c,
    uint32_t a0, uint32_t a1, uint32_t a2, uint32_t a3,
    uint32_t b0, uint32_t b1)
{
    asm volatile(
        "mma.sync.aligned.m16n8k8.row.col.f32.tf32.tf32.f32 "
        "{%0,%1,%2,%3}, {%4,%5,%6,%7}, {%8,%9}, {%0,%1,%2,%3};"
        : "+f"(c[0]), "+f"(c[1]), "+f"(c[2]), "+f"(c[3])
        : "r"(a0), "r"(a1), "r"(a2), "r"(a3), "r"(b0), "r"(b1));
}

__device__ __forceinline__ float elu1(float v) {
    return v > 0.f ? v : (__expf(v) - 1.f);
}

__device__ __forceinline__ void cp16(uint32_t smem_addr, const void* gptr) {
    asm volatile("cp.async.ca.shared.global [%0], [%1], 16;\n"
                 :: "r"(smem_addr), "l"(gptr));
}
#define CP_COMMIT() asm volatile("cp.async.commit_group;\n" ::: "memory")
template <int N> __device__ __forceinline__ void cp_wait() {
    asm volatile("cp.async.wait_group %0;\n" :: "n"(N) : "memory");
}
#define BAR_SYNC(id) asm volatile("bar.sync %0, 128;" :: "r"(id) : "memory")

// =====================================================================
// K0: pack weights (tf32-converted) + wa vectors
// =====================================================================
__global__ void pack_kernel(const float* __restrict__ g1_Wh, const float* __restrict__ gf_Wh,
                            const float* __restrict__ g1_Wout, const float* __restrict__ g1_aout,
                            const float* __restrict__ gf_Wout, const float* __restrict__ hb_W)
{
    int t = threadIdx.x, bid = blockIdx.x;
    int gid = bid * 256 + t;
    for (int idx = gid; idx < 128 * 256; idx += 64 * 256) {
        int k = idx >> 8, c = idx & 255;
        float v = (c < 128) ? g1_Wh[(c >> 5) * 4096 + k * 32 + (c & 31)]
                            : gf_Wh[((c - 128) >> 5) * 4096 + k * 32 + (c & 31)];
        g_Bheads[idx] = tf32f(v);
    }
    for (int idx = gid; idx < 256 * 512; idx += 64 * 256) {
        int k = idx >> 9, n = idx & 511;
        g_BhbT[idx] = tf32f(hb_W[n * 256 + k]);
    }
    for (int idx = gid; idx < 128 * 512; idx += 64 * 256)
        g_Wout32[idx] = tf32f(g1_Wout[idx]);
    for (int idx = gid; idx < 128 * 32; idx += 64 * 256)
        g_gfW32[idx] = tf32f(gf_Wout[idx]);
    if (bid == 0) {
        int wp = t >> 5, ln = t & 31;
        for (int d = wp; d < 256; d += 8) {
            int k = d & 127, half = d >> 7;
            const float* ap = g1_aout + half * 512;
            const float* wr = g1_Wout + (size_t)k * 512;
            float acc = 0.f;
            for (int c = ln; c < 512; c += 32) acc = fmaf(wr[c], ap[c], acc);
            #pragma unroll
            for (int o = 16; o; o >>= 1) acc += __shfl_down_sync(FULLM, acc, o);
            if (ln == 0) g_wa[half * 128 + k] = acc;
        }
    }
}

// =====================================================================
// TF32 GEMM (used for b_all only): C = A @ B, B PRE-CONVERTED.
// =====================================================================
#define LDA 36
#define LDB 136

__global__ __launch_bounds__(256) void gemm_tf32(
    const float* __restrict__ A, const float* __restrict__ B, float* __restrict__ C,
    int M, int K, int N)
{
    __shared__ uint32_t As[128 * LDA];
    __shared__ uint32_t Bs[32 * LDB];
    int t = threadIdx.x;
    int lane = t & 31, w = t >> 5;
    int wm = w & 3, wn = w >> 2;
    int bm = blockIdx.y * 128, bn = blockIdx.x * 128;
    int r = lane >> 2, cq = lane & 3;

    float acc[2][8][4];
    #pragma unroll
    for (int mi = 0; mi < 2; mi++)
        #pragma unroll
        for (int ni = 0; ni < 8; ni++)
            #pragma unroll
            for (int j = 0; j < 4; j++) acc[mi][ni][j] = 0.f;

    for (int k0 = 0; k0 < K; k0 += 32) {
        #pragma unroll
        for (int l = 0; l < 4; l++) {
            int idx = t + l * 256;
            int row = idx >> 3, q = idx & 7;
            float4 v = *reinterpret_cast<const float4*>(A + (size_t)(bm + row) * K + k0 + q * 4);
            uint32_t* p = &As[row * LDA + q * 4];
            p[0] = f2tf32(v.x); p[1] = f2tf32(v.y); p[2] = f2tf32(v.z); p[3] = f2tf32(v.w);
        }
        #pragma unroll
        for (int l = 0; l < 4; l++) {
            int idx = t + l * 256;
            int row = idx >> 5, q = idx & 31;
            uint4 v = *reinterpret_cast<const uint4*>(B + (size_t)(k0 + row) * N + bn + q * 4);
            uint32_t* p = &Bs[row * LDB + q * 4];
            p[0] = v.x; p[1] = v.y; p[2] = v.z; p[3] = v.w;
        }
        __syncthreads();
        #pragma unroll
        for (int kk = 0; kk < 32; kk += 8) {
            uint32_t a[2][4];
            #pragma unroll
            for (int mi = 0; mi < 2; mi++) {
                int rb = wm * 32 + mi * 16;
                a[mi][0] = As[(rb + r) * LDA + kk + cq];
                a[mi][1] = As[(rb + r + 8) * LDA + kk + cq];
                a[mi][2] = As[(rb + r) * LDA + kk + cq + 4];
                a[mi][3] = As[(rb + r + 8) * LDA + kk + cq + 4];
            }
            #pragma unroll
            for (int ni = 0; ni < 8; ni++) {
                int cb = wn * 64 + ni * 8;
                uint32_t b0 = Bs[(kk + cq) * LDB + cb + r];
                uint32_t b1 = Bs[(kk + 4 + cq) * LDB + cb + r];
                #pragma unroll
                for (int mi = 0; mi < 2; mi++)
                    mma_16n8k8(acc[mi][ni], a[mi][0], a[mi][1], a[mi][2], a[mi][3], b0, b1);
            }
        }
        __syncthreads();
    }
    #pragma unroll
    for (int mi = 0; mi < 2; mi++) {
        int rb = bm + wm * 32 + mi * 16 + r;
        #pragma unroll
        for (int ni = 0; ni < 8; ni++) {
            int cb = bn + wn * 64 + ni * 8 + 2 * cq;
            *reinterpret_cast<float2*>(C + (size_t)rb * N + cb) =
                make_float2(acc[mi][ni][0], acc[mi][ni][1]);
            *reinterpret_cast<float2*>(C + (size_t)(rb + 8) * N + cb) =
                make_float2(acc[mi][ni][2], acc[mi][ni][3]);
        }
    }
}

// =====================================================================
// K1: FUSED head-projection + attention, warp-specialized tail.
// Warps 0-3: g1 path (scores -> att2 -> z). Warps 4-7: gf path.
// =====================================================================
#define XCP 132

__global__ __launch_bounds__(256) void attn_kernel(
    const float* __restrict__ obs_g, const float* __restrict__ adj_g,
    const float* __restrict__ g1_ah, const float* __restrict__ gf_ah,
    const float* __restrict__ gf_aout)
{
    int b = blockIdx.x;
    int t = threadIdx.x;
    int lane = t & 31, w = t >> 5;
    int r = lane >> 2, cq = lane & 3;

    __shared__ float buf1[NA][XCP];
    __shared__ float xcf[NA][XCP];
    __shared__ float att_w[8][NA][17];
    __shared__ float adj[NA][NA];
    __shared__ float f1s[NA], f2s[NA];
    __shared__ float att2s[NA][17];
    __shared__ float whf[NA][34];

    {
        const float4* src = reinterpret_cast<const float4*>(obs_g + (size_t)b * 2048);
        #pragma unroll
        for (int l = 0; l < 2; l++) {
            int idx4 = t + l * 256;
            int row = idx4 >> 5, c4 = (idx4 & 31) * 4;
            float4 v = src[idx4];
            buf1[row][c4]     = tf32f(v.x);
            buf1[row][c4 + 1] = tf32f(v.y);
            buf1[row][c4 + 2] = tf32f(v.z);
            buf1[row][c4 + 3] = tf32f(v.w);
        }
    }
    adj[t >> 4][t & 15] = adj_g[(size_t)b * 256 + t];
    __syncthreads();

    int h = w;
    float acc1[4][4];
    #pragma unroll
    for (int nt = 0; nt < 4; nt++)
        #pragma unroll
        for (int q = 0; q < 4; q++) acc1[nt][q] = 0.f;
    #pragma unroll
    for (int ks = 0; ks < 16; ks++) {
        int kk = ks * 8;
        uint32_t a0 = __float_as_uint(buf1[r][kk + cq]);
        uint32_t a1 = __float_as_uint(buf1[r + 8][kk + cq]);
        uint32_t a2 = __float_as_uint(buf1[r][kk + cq + 4]);
        uint32_t a3 = __float_as_uint(buf1[r + 8][kk + cq + 4]);
        #pragma unroll
        for (int nt = 0; nt < 4; nt++) {
            int cb = h * 32 + nt * 8;
            uint32_t b0 = __float_as_uint(__ldg(&g_Bheads[(kk + cq) * 256 + cb + r]));
            uint32_t b1 = __float_as_uint(__ldg(&g_Bheads[(kk + 4 + cq) * 256 + cb + r]));
            mma_16n8k8(acc1[nt], a0, a1, a2, a3, b0, b1);
        }
    }

    float facc;
    {
        const float* av = (h < 4) ? (g1_ah + h * 64) : (gf_ah + (h - 4) * 64);
        float pf1r = 0.f, pf1r8 = 0.f, pf2r = 0.f, pf2r8 = 0.f;
        #pragma unroll
        for (int nt = 0; nt < 4; nt++) {
            float2 a1v = __ldg(reinterpret_cast<const float2*>(av + nt * 8 + 2 * cq));
            float2 a2v = __ldg(reinterpret_cast<const float2*>(av + 32 + nt * 8 + 2 * cq));
            pf1r  = fmaf(acc1[nt][0], a1v.x, fmaf(acc1[nt][1], a1v.y, pf1r));
            pf1r8 = fmaf(acc1[nt][2], a1v.x, fmaf(acc1[nt][3], a1v.y, pf1r8));
            pf2r  = fmaf(acc1[nt][0], a2v.x, fmaf(acc1[nt][1], a2v.y, pf2r));
            pf2r8 = fmaf(acc1[nt][2], a2v.x, fmaf(acc1[nt][3], a2v.y, pf2r8));
        }
        #pragma unroll
        for (int mk = 1; mk <= 2; mk <<= 1) {
            pf1r  += __shfl_xor_sync(FULLM, pf1r,  mk);
            pf1r8 += __shfl_xor_sync(FULLM, pf1r8, mk);
            pf2r  += __shfl_xor_sync(FULLM, pf2r,  mk);
            pf2r8 += __shfl_xor_sync(FULLM, pf2r8, mk);
        }
        int j = lane & 15, half = lane >> 4;
        int src = (j & 7) * 4;
        float s1 = __shfl_sync(FULLM, pf1r,  src);
        float s2 = __shfl_sync(FULLM, pf1r8, src);
        float s3 = __shfl_sync(FULLM, pf2r,  src);
        float s4 = __shfl_sync(FULLM, pf2r8, src);
        facc = half ? ((j < 8) ? s3 : s4) : ((j < 8) ? s1 : s2);
    }
    __syncthreads();

    {
        int j = lane & 15;
        float f2j = __shfl_sync(FULLM, facc, 16 + j);
        float attc[NA];
        float m = -INFINITY;
        #pragma unroll
        for (int i = 0; i < NA; i++) {
            float f1i = __shfl_sync(FULLM, facc, i);
            float e = f1i + f2j;
            e = e > 0.f ? e : ALPHA * e;
            e = (adj[i][j] > 0.f) ? e : NEGV;
            attc[i] = e; m = fmaxf(m, e);
        }
        float s = 0.f;
        #pragma unroll
        for (int i = 0; i < NA; i++) { float x = __expf(attc[i] - m); attc[i] = x; s += x; }
        float inv = 1.f / s;
        if (lane < 16) {
            #pragma unroll
            for (int i = 0; i < NA; i++) att_w[h][i][j] = tf32f(attc[i] * inv);
        }
        __syncwarp();
    }

    {
        float acc2[4][4];
        #pragma unroll
        for (int nt = 0; nt < 4; nt++)
            #pragma unroll
            for (int q = 0; q < 4; q++) acc2[nt][q] = 0.f;
        int src0 = cq * 4 + (r >> 1);
        int src1 = (cq + 4) * 4 + (r >> 1);
        bool odd = (r & 1);
        #pragma unroll
        for (int ks2 = 0; ks2 < 2; ks2++) {
            int kk2 = ks2 * 8;
            uint32_t a0 = __float_as_uint(att_w[h][r][kk2 + cq]);
            uint32_t a1 = __float_as_uint(att_w[h][r + 8][kk2 + cq]);
            uint32_t a2 = __float_as_uint(att_w[h][r][kk2 + cq + 4]);
            uint32_t a3 = __float_as_uint(att_w[h][r + 8][kk2 + cq + 4]);
            #pragma unroll
            for (int nt = 0; nt < 4; nt++) {
                float lo = acc1[nt][ks2 * 2];
                float hi = acc1[nt][ks2 * 2 + 1];
                float v0l = __shfl_sync(FULLM, lo, src0);
                float v0h = __shfl_sync(FULLM, hi, src0);
                float v1l = __shfl_sync(FULLM, lo, src1);
                float v1h = __shfl_sync(FULLM, hi, src1);
                uint32_t b0 = f2tf32(odd ? v0h : v0l);
                uint32_t b1 = f2tf32(odd ? v1h : v1l);
                mma_16n8k8(acc2[nt], a0, a1, a2, a3, b0, b1);
            }
        }
        float* base = (h < 4) ? &buf1[0][h * 32] : &xcf[0][(h - 4) * 32];
        #pragma unroll
        for (int nt = 0; nt < 4; nt++) {
            int col = nt * 8 + 2 * cq;
            *reinterpret_cast<float2*>(base + r * XCP + col) =
                make_float2(tf32f(elu1(acc2[nt][0])), tf32f(elu1(acc2[nt][1])));
            *reinterpret_cast<float2*>(base + (r + 8) * XCP + col) =
                make_float2(tf32f(elu1(acc2[nt][2])), tf32f(elu1(acc2[nt][3])));
        }
    }
    __syncthreads();   // xc1 (buf1) and xcf complete; groups diverge below

    if (w < 4) {
        // ============ GROUP A (warps 0-3): g1 path ============
        #pragma unroll
        for (int rr = 0; rr < 8; rr++) {
            int d = w * 8 + rr;              // 0..31
            int i = d & 15, half = d >> 4;
            const float* wav = g_wa + half * 128;
            float acc = 0.f;
            #pragma unroll
            for (int k = lane; k < 128; k += 32) acc = fmaf(buf1[i][k], wav[k], acc);
            #pragma unroll
            for (int o = 16; o; o >>= 1) acc += __shfl_down_sync(FULLM, acc, o);
            if (lane == 0) { if (half) f2s[i] = acc; else f1s[i] = acc; }
        }
        BAR_SYNC(1);
        if (t < NA) {
            int j = t;
            float ev[NA]; float m = -INFINITY;
            #pragma unroll
            for (int i = 0; i < NA; i++) {
                float e = f1s[i] + f2s[j];
                e = e > 0.f ? e : ALPHA * e;
                e = (adj[i][j] > 0.f) ? e : NEGV;
                ev[i] = e; m = fmaxf(m, e);
            }
            float s = 0.f;
            #pragma unroll
            for (int i = 0; i < NA; i++) { float x = __expf(ev[i] - m); ev[i] = x; s += x; }
            float inv = 1.f / s;
            #pragma unroll
            for (int i = 0; i < NA; i++) att2s[i][j] = tf32f(ev[i] * inv);
        }
        BAR_SYNC(1);
        // z: warp w -> cols [32w, 32w+32)
        {
            float acc[4][4];
            #pragma unroll
            for (int nt = 0; nt < 4; nt++)
                #pragma unroll
                for (int q = 0; q < 4; q++) acc[nt][q] = 0.f;
            #pragma unroll
            for (int ks = 0; ks < 2; ks++) {
                int kk = ks * 8;
                uint32_t a0 = __float_as_uint(att2s[r][kk + cq]);
                uint32_t a1 = __float_as_uint(att2s[r + 8][kk + cq]);
                uint32_t a2 = __float_as_uint(att2s[r][kk + cq + 4]);
                uint32_t a3 = __float_as_uint(att2s[r + 8][kk + cq + 4]);
                #pragma unroll
                for (int nt = 0; nt < 4; nt++) {
                    int cb = w * 32 + nt * 8;
                    uint32_t b0 = __float_as_uint(buf1[kk + cq][cb + r]);
                    uint32_t b1 = __float_as_uint(buf1[kk + 4 + cq][cb + r]);
                    mma_16n8k8(acc[nt], a0, a1, a2, a3, b0, b1);
                }
            }
            float* zdst = g_z + (size_t)b * 2048;
            #pragma unroll
            for (int nt = 0; nt < 4; nt++) {
                int col = w * 32 + nt * 8 + 2 * cq;
                *reinterpret_cast<float2*>(zdst + r * 128 + col) =
                    make_float2(tf32f(acc[nt][0]), tf32f(acc[nt][1]));
                *reinterpret_cast<float2*>(zdst + (r + 8) * 128 + col) =
                    make_float2(tf32f(acc[nt][2]), tf32f(acc[nt][3]));
            }
        }
    } else {
        // ============ GROUP B (warps 4-7): gf path ============
        {
            int cb = (w - 4) * 8;
            float acc[4] = {0.f, 0.f, 0.f, 0.f};
            #pragma unroll
            for (int ks = 0; ks < 16; ks++) {
                int kk = ks * 8;
                uint32_t a0 = __float_as_uint(xcf[r][kk + cq]);
                uint32_t a1 = __float_as_uint(xcf[r + 8][kk + cq]);
                uint32_t a2 = __float_as_uint(xcf[r][kk + cq + 4]);
                uint32_t a3 = __float_as_uint(xcf[r + 8][kk + cq + 4]);
                uint32_t b0 = __float_as_uint(g_gfW32[(kk + cq) * 32 + cb + r]);
                uint32_t b1 = __float_as_uint(g_gfW32[(kk + 4 + cq) * 32 + cb + r]);
                mma_16n8k8(acc, a0, a1, a2, a3, b0, b1);
            }
            int col = cb + 2 * cq;
            *reinterpret_cast<float2*>(&whf[r][col]) = make_float2(acc[0], acc[1]);
            *reinterpret_cast<float2*>(&whf[r + 8][col]) = make_float2(acc[2], acc[3]);
        }
        BAR_SYNC(2);   // single arrival by all 128 threads of group B
        if (w == 4) {
            int d = lane & 15, half = lane >> 4;
            const float* av = gf_aout + half * 32;
            float fac = 0.f;
            #pragma unroll
            for (int c = 0; c < 32; c++) fac = fmaf(whf[d][c], av[c], fac);
            int j = lane & 15;
            float f2j = __shfl_sync(FULLM, fac, 16 + j);
            float attc[NA];
            float m = -INFINITY;
            #pragma unroll
            for (int i = 0; i < NA; i++) {
                float f1i = __shfl_sync(FULLM, fac, i);
                float e = f1i + f2j;
                e = e > 0.f ? e : ALPHA * e;
                e = (adj[i][j] > 0.f) ? e : NEGV;
                attc[i] = e; m = fmaxf(m, e);
            }
            float s = 0.f;
            #pragma unroll
            for (int i = 0; i < NA; i++) { float x = __expf(attc[i] - m); attc[i] = x; s += x; }
            float inv = 1.f / s;
            #pragma unroll
            for (int i = 0; i < NA; i++) attc[i] *= inv;
            int c = lane;
            float o2[NA];
            float mm = -INFINITY;
            #pragma unroll
            for (int i = 0; i < NA; i++) {
                float acc = 0.f;
                #pragma unroll
                for (int n = 0; n < NA; n++) {
                    float a_in = __shfl_sync(FULLM, attc[i], n);
                    acc = fmaf(a_in, whf[n][c], acc);
                }
                acc = elu1(acc);
                o2[i] = acc; mm = fmaxf(mm, acc);
            }
            float ss = 0.f;
            #pragma unroll
            for (int i = 0; i < NA; i++) ss += __expf(o2[i] - mm);
            float lse = mm + __logf(ss);
            #pragma unroll
            for (int i = 0; i < NA; i++)
                g_wf[(size_t)b * 512 + i * 32 + c] = fabsf(o2[i] - lse);
        }
    }
}

// =====================================================================
// K2: GEMM3 half-N CTAs (unchanged from R13).
// =====================================================================
#define LDB3H 264
#define ASTG  (64 * LDA)
#define BSTGH (32 * LDB3H)

extern __shared__ char g3smem[];

__global__ __launch_bounds__(256, 2) void gemm3_half_kernel(
    const float* __restrict__ A,
    const float* __restrict__ Wout,
    const float* __restrict__ agent_qs)
{
    uint32_t* Sm = reinterpret_cast<uint32_t*>(g3smem);
    float*    Ds = reinterpret_cast<float*>(g3smem);
    uint32_t smem_u32 = (uint32_t)__cvta_generic_to_shared(g3smem);

    __shared__ float qs_s[4][NA];

    int t = threadIdx.x;
    int lane = t & 31, w = t >> 5;
    int wm = w & 1, wn = w >> 1;
    int r = lane >> 2, cq = lane & 3;
    int half = blockIdx.x;
    int bm = blockIdx.y * 64;
    int b0 = blockIdx.y * 4;
    int bn = half * 256;

    if (t < 64) qs_s[t >> 4][t & 15] = agent_qs[(size_t)(b0 + (t >> 4)) * NA + (t & 15)];

    int arow = t >> 3, aq = t & 7;
    const float* agsrc = A + (size_t)(bm + arow) * 128 + aq * 4;
    const float* agsrc2 = A + (size_t)(bm + arow + 32) * 128 + aq * 4;
    uint32_t adst1 = (uint32_t)(arow * LDA + aq * 4) * 4;
    uint32_t adst2 = (uint32_t)((arow + 32) * LDA + aq * 4) * 4;

    #define LOAD_STAGE_H(s, k0)                                                 \
        do {                                                                    \
            uint32_t abase = smem_u32 + (uint32_t)((s) * ASTG) * 4;             \
            cp16(abase + adst1, agsrc + (k0));                                  \
            cp16(abase + adst2, agsrc2 + (k0));                                 \
            uint32_t bbase = smem_u32 + (uint32_t)(2 * ASTG + (s) * BSTGH) * 4; \
            _Pragma("unroll")                                                   \
            for (int l = 0; l < 8; l++) {                                       \
                int idx = t + l * 256;                                          \
                int brow = idx >> 6, bq = idx & 63;                             \
                cp16(bbase + (uint32_t)(brow * LDB3H + bq * 4) * 4,             \
                     Wout + (size_t)((k0) + brow) * 512 + bn + bq * 4);         \
            }                                                                   \
            CP_COMMIT();                                                        \
        } while (0)

    float acc[2][8][4];
    #pragma unroll
    for (int mi = 0; mi < 2; mi++)
        #pragma unroll
        for (int ni = 0; ni < 8; ni++)
            #pragma unroll
            for (int j = 0; j < 4; j++) acc[mi][ni][j] = 0.f;

    LOAD_STAGE_H(0, 0);
    LOAD_STAGE_H(1, 32);

    #pragma unroll
    for (int it = 0; it < 4; it++) {
        int s = it & 1;
        if (it < 3) cp_wait<1>(); else cp_wait<0>();
        __syncthreads();
        const uint32_t* As = Sm + s * ASTG;
        const uint32_t* Bs = Sm + 2 * ASTG + s * BSTGH;
        #pragma unroll
        for (int kk = 0; kk < 32; kk += 8) {
            uint32_t a[2][4];
            #pragma unroll
            for (int mi = 0; mi < 2; mi++) {
                int rb = wm * 32 + mi * 16;
                a[mi][0] = As[(rb + r) * LDA + kk + cq];
                a[mi][1] = As[(rb + r + 8) * LDA + kk + cq];
                a[mi][2] = As[(rb + r) * LDA + kk + cq + 4];
                a[mi][3] = As[(rb + r + 8) * LDA + kk + cq + 4];
            }
            #pragma unroll
            for (int ni = 0; ni < 8; ni++) {
                int cb = wn * 64 + ni * 8;
                uint32_t b0r = Bs[(kk + cq) * LDB3H + cb + r];
                uint32_t b1r = Bs[(kk + 4 + cq) * LDB3H + cb + r];
                #pragma unroll
                for (int mi = 0; mi < 2; mi++)
                    mma_16n8k8(acc[mi][ni], a[mi][0], a[mi][1], a[mi][2], a[mi][3], b0r, b1r);
            }
        }
        __syncthreads();
        if (it + 2 < 4) LOAD_STAGE_H(s, (it + 2) * 32);
    }

    #pragma unroll
    for (int mi = 0; mi < 2; mi++) {
        int row0 = wm * 32 + mi * 16 + r;
        #pragma unroll
        for (int ni = 0; ni < 8; ni++) {
            int col = wn * 64 + ni * 8 + 2 * cq;
            *reinterpret_cast<float2*>(&Ds[row0 * 256 + col]) =
                make_float2(elu1(acc[mi][ni][0]), elu1(acc[mi][ni][1]));
            *reinterpret_cast<float2*>(&Ds[(row0 + 8) * 256 + col]) =
                make_float2(elu1(acc[mi][ni][2]), elu1(acc[mi][ni][3]));
        }
    }
    __syncthreads();

    #pragma unroll
    for (int p = 0; p < 4; p++) {
        int tt = t + p * 256;
        int bl = tt >> 8, c = tt & 255;
        float* col = Ds + (bl * 16) * 256 + c;
        float v[NA]; float m = -INFINITY;
        #pragma unroll
        for (int i = 0; i < NA; i++) { v[i] = col[i * 256]; m = fmaxf(m, v[i]); }
        float s = 0.f;
        #pragma unroll
        for (int i = 0; i < NA; i++) s += __expf(v[i] - m);
        float lse = m + __logf(s);
        #pragma unroll
        for (int i = 0; i < NA; i++) col[i * 256] = fabsf(v[i] - lse);
    }
    __syncthreads();

    {
        int e = lane;
        #pragma unroll
        for (int ai = 0; ai < 2; ai++) {
            int i = w + ai * 8;
            #pragma unroll
            for (int bl = 0; bl < 4; bl++) {
                const float* row = Ds + (bl * 16 + i) * 256;
                float p = 0.f;
                #pragma unroll
                for (int np = 0; np < 8; np++)
                    p = fmaf(qs_s[bl][8 * half + np], row[np * 32 + e], p);
                g_hidp[(((size_t)(b0 + bl) * 2 + half) * 16 + i) * 32 + e] = p;
            }
        }
    }
}

// =====================================================================
// K3: final mix (unchanged from R13).
// =====================================================================
__global__ __launch_bounds__(256) void mix_final_kernel(
    const float* __restrict__ states,
    const float* __restrict__ wn_w, const float* __restrict__ wn_b,
    const float* __restrict__ hb_b,
    const float* __restrict__ v1_w, const float* __restrict__ v1_b,
    const float* __restrict__ v2_w, const float* __restrict__ v2_b,
    float* __restrict__ out)
{
    int b = blockIdx.x;
    int t = threadIdx.x;
    int lane = t & 31, w = t >> 5;

    __shared__ float st[STATE];
    __shared__ float yv[NA], disv[NA], vpart[32];

    st[t] = (t < 256) ? states[(size_t)b * 256 + t] : 0.f;
    __syncthreads();

    {
        int e = lane;
        #pragma unroll
        for (int ai = 0; ai < 2; ai++) {
            int i = w + ai * 8;
            size_t base0 = (((size_t)b * 2 + 0) * 16 + i) * 32 + e;
            size_t base1 = (((size_t)b * 2 + 1) * 16 + i) * 32 + e;
            float hp = g_hidp[base0] + g_hidp[base1]
                     + g_ball[(size_t)b * 512 + i * 32 + e] + hb_b[i * 32 + e];
            hp = elu1(hp);
            float prod = hp * g_wf[(size_t)b * 512 + i * 32 + e];
            #pragma unroll
            for (int o = 16; o; o >>= 1) prod += __shfl_down_sync(FULLM, prod, o);
            if (lane == 0) yv[i] = prod;
        }
    }

    {
        #pragma unroll
        for (int rr = 0; rr < 2; rr++) {
            int n = w * 2 + rr;
            float acc2 = 0.f;
            #pragma unroll
            for (int s_ = lane; s_ < 256; s_ += 32)
                acc2 = fmaf(st[s_], wn_w[n * 256 + s_], acc2);
            #pragma unroll
            for (int o = 16; o; o >>= 1) acc2 += __shfl_down_sync(FULLM, acc2, o);
            if (lane == 0) disv[n] = fabsf(acc2 + wn_b[n]);
        }
        #pragma unroll
        for (int rr = 0; rr < 4; rr++) {
            int n = w * 4 + rr;
            float acc2 = 0.f;
            #pragma unroll
            for (int s_ = lane; s_ < 256; s_ += 32)
                acc2 = fmaf(st[s_], v1_w[n * 256 + s_], acc2);
            #pragma unroll
            for (int o = 16; o; o >>= 1) acc2 += __shfl_down_sync(FULLM, acc2, o);
            if (lane == 0) vpart[n] = fmaxf(acc2 + v1_b[n], 0.f);
        }
    }
    __syncthreads();

    if (t == 0) {
        float v = v2_b[0];
        #pragma unroll
        for (int h2 = 0; h2 < 32; h2++) v = fmaf(vpart[h2], v2_w[h2], v);
        float q = v;
        #pragma unroll
        for (int n = 0; n < NA; n++) q = fmaf(yv[n], disv[n], q);
        out[b] = q;
    }
}

// =====================================================================
extern "C" void kernel_launch(void* const* d_in, const int* in_sizes, int n_in,
                              void* d_out, int out_size)
{
    const float* agent_qs = (const float*)d_in[0];
    const float* states   = (const float*)d_in[1];
    const float* obs_ls   = (const float*)d_in[2];
    const float* adj_ls   = (const float*)d_in[3];
    const float* wn_w     = (const float*)d_in[4];
    const float* wn_b     = (const float*)d_in[5];
    const float* g1_Wh    = (const float*)d_in[6];
    const float* g1_ah    = (const float*)d_in[7];
    const float* g1_Wout  = (const float*)d_in[8];
    const float* g1_aout  = (const float*)d_in[9];
    const float* gf_Wh    = (const float*)d_in[10];
    const float* gf_ah    = (const float*)d_in[11];
    const float* gf_Wout  = (const float*)d_in[12];
    const float* gf_aout  = (const float*)d_in[13];
    const float* hb_W     = (const float*)d_in[14];
    const float* hb_b     = (const float*)d_in[15];
    const float* v1_w     = (const float*)d_in[16];
    const float* v1_b     = (const float*)d_in[17];
    const float* v2_w     = (const float*)d_in[18];
    const float* v2_b     = (const float*)d_in[19];
    float* out = (float*)d_out;

    float *p_z, *p_ball, *p_BhbT, *p_Wout32;
    cudaGetSymbolAddress((void**)&p_z,      g_z);
    cudaGetSymbolAddress((void**)&p_ball,   g_ball);
    cudaGetSymbolAddress((void**)&p_BhbT,   g_BhbT);
    cudaGetSymbolAddress((void**)&p_Wout32, g_Wout32);

    const int G3H_SMEM = (2 * ASTG + 2 * BSTGH) * 4;   // 86,016 B
    cudaFuncSetAttribute(gemm3_half_kernel,
                         cudaFuncAttributeMaxDynamicSharedMemorySize, G3H_SMEM);

    pack_kernel<<<64, 256>>>(g1_Wh, gf_Wh, g1_Wout, g1_aout, gf_Wout, hb_W);

    // b_all = states(8192x256) @ hb_W^T(256x512)
    gemm_tf32<<<dim3(4, 64), 256>>>(states, p_BhbT, p_ball, BTOT, 256, 512);

    // fused head-projection + attention (warp-specialized tail)
    attn_kernel<<<BTOT, 256>>>(obs_ls, adj_ls, g1_ah, gf_ah, gf_aout);

    // D = Z @ Wout in half-N CTAs -> elu/logsoftmax/abs -> partial hidden
    gemm3_half_kernel<<<dim3(2, 2048), 256, G3H_SMEM>>>(p_z, p_Wout32, agent_qs);

    // combine partials + ball -> elu -> y; dis, V, q
    mix_final_kernel<<<BTOT, 256>>>(states, wn_w, wn_b, hb_b,
                                    v1_w, v1_b, v2_w, v2_b, out);
}